// round 13
// baseline (speedup 1.0000x reference)
#include <cuda_runtime.h>

// out[b,e] = sparsity[b,e] * sum_h ( sum_m hidden[b,m,h] ) * ( sum_n weight[e,h,n] )
// A=1, B=32, M=32, H=1024, E=8, N=1024.
//
// SINGLE kernel, ZERO duplication, 256 blocks x 256 threads (~2 blocks/SM).
// Block = h-chunk of 4 (owns all n for its 4 h's, and hidden's 4-h column).
//   Phase H (first): thread (b, mg) sums 4 m-rows of one float4 (4 h's).
//   Phase W: warp e streams 4 full rows as 8 batches x 4 independent LDG.128
//            (4 accumulator chains -- the proven R5 streaming shape).
//   Phase D: thread (b,e) folds the 8 mg-partials into the dot, 1 RED/thread.
//   Tail: last block (done counter) writes out = accum * sparsity, resets.

#define Bn 32
#define Mn 32
#define Hn 1024
#define En 8
#define Nn 1024
#define NBLK (Hn / 4)    // 256

__device__ float g_accum[Bn * En];   // zeroed at load; reset by tail each run
__device__ int   g_done = 0;

__global__ void __launch_bounds__(256) einsum_fused_kernel(
    const float* __restrict__ hidden,
    const float* __restrict__ sparsity,
    const float* __restrict__ weight,
    float* __restrict__ out)
{
    const int tid  = threadIdx.x;
    const int lane = tid & 31;
    const int wid  = tid >> 5;           // = e for phase W
    const int bid  = blockIdx.x;         // h-chunk: h0 = bid*4
    const int h0   = bid * 4;

    __shared__ float4 sm_hp[8][32];      // [mg][b]: partial over 4 m-rows (4 h floats)
    __shared__ float4 sm_ws[8];          // ws[e][0..3]
    __shared__ int    sm_last;

    // ---- Phase H FIRST: thread (b = tid>>3, mg = tid&7) sums 4 m-rows ----
    {
        const int b  = tid >> 3;
        const int mg = tid & 7;
        const float4* H4 = reinterpret_cast<const float4*>(hidden);
        const size_t base = (size_t)(b * Mn + mg * 4) * (Hn / 4) + bid;
        float4 v0 = H4[base];
        float4 v1 = H4[base + (Hn / 4)];
        float4 v2 = H4[base + 2 * (Hn / 4)];
        float4 v3 = H4[base + 3 * (Hn / 4)];
        sm_hp[mg][b] = make_float4((v0.x + v1.x) + (v2.x + v3.x),
                                   (v0.y + v1.y) + (v2.y + v3.y),
                                   (v0.z + v1.z) + (v2.z + v3.z),
                                   (v0.w + v1.w) + (v2.w + v3.w));
    }

    // ---- Phase W: warp e = wid streams rows (e, h0..h0+4), all 1024 n ----
    {
        const float4* W4 = reinterpret_cast<const float4*>(weight);
        const size_t rb  = (size_t)(wid * Hn + h0) * (Nn / 4) + lane;
        float s0 = 0.f, s1 = 0.f, s2 = 0.f, s3 = 0.f;
        #pragma unroll
        for (int k = 0; k < 8; k++) {            // 8 batches of 4 indep LDG.128
            float4 a = W4[rb + 0 * (Nn / 4) + k * 32];
            float4 b = W4[rb + 1 * (Nn / 4) + k * 32];
            float4 c = W4[rb + 2 * (Nn / 4) + k * 32];
            float4 d = W4[rb + 3 * (Nn / 4) + k * 32];
            s0 += (a.x + a.y) + (a.z + a.w);
            s1 += (b.x + b.y) + (b.z + b.w);
            s2 += (c.x + c.y) + (c.z + c.w);
            s3 += (d.x + d.y) + (d.z + d.w);
        }
        #pragma unroll
        for (int off = 16; off > 0; off >>= 1) {
            s0 += __shfl_xor_sync(0xffffffffu, s0, off);
            s1 += __shfl_xor_sync(0xffffffffu, s1, off);
            s2 += __shfl_xor_sync(0xffffffffu, s2, off);
            s3 += __shfl_xor_sync(0xffffffffu, s3, off);
        }
        if (lane == 0) sm_ws[wid] = make_float4(s0, s1, s2, s3);
    }
    __syncthreads();    // the ONE barrier in the main path

    // ---- Phase D: thread (b = tid>>3, e = tid&7): fold mg-sum into dot ----
    {
        const int b = tid >> 3;
        const int e = tid & 7;
        const float4 w = sm_ws[e];
        float p = 0.f;
        #pragma unroll
        for (int g = 0; g < 8; g++) {
            float4 v = sm_hp[g][b];
            p += v.x * w.x + v.y * w.y + v.z * w.z + v.w * w.w;
        }
        atomicAdd(&g_accum[tid], p);    // index = b*8+e = tid
    }

    // ---- Tail: last block finalizes ----
    __threadfence();
    __syncthreads();
    if (tid == 0)
        sm_last = (atomicAdd(&g_done, 1) == NBLK - 1) ? 1 : 0;
    __syncthreads();
    if (sm_last) {
        __threadfence();
        const float v = __ldcg(&g_accum[tid]);
        out[tid] = v * sparsity[tid];
        g_accum[tid] = 0.f;             // reset for next graph replay
        if (tid == 0) g_done = 0;
    }
}

extern "C" void kernel_launch(void* const* d_in, const int* in_sizes, int n_in,
                              void* d_out, int out_size)
{
    const float* hidden   = (const float*)d_in[0];
    const float* sparsity = (const float*)d_in[1];
    const float* weight   = (const float*)d_in[2];
    float* out = (float*)d_out;

    einsum_fused_kernel<<<NBLK, 256>>>(hidden, sparsity, weight, out);
}